// round 9
// baseline (speedup 1.0000x reference)
#include <cuda_runtime.h>
#include <cuda.h>
#include <cstdint>

// ---------------------------------------------------------------------------
// Problem constants (shapes fixed by the dataset)
// ---------------------------------------------------------------------------
#define TOKENS   2048
#define KDIM     4096
#define MDIM     4096
#define NB       1024
#define NROW     64          // MDIM / 64
#define MT       128         // token tile
#define NTILE    (TOKENS / MT)   // 16
#define NTHREADS 256         // 8 warps: 4 token-groups x 2 out-groups

// SMEM map (header + 2 stages)
#define MB_FULL0    8
#define MB_FULL1    16
#define SMEM_BIAS   64       // 64 floats
#define SMEM_COLS   512      // up to 1024 ints (col offsets, elements)
#define SMEM_BLK    4608     // up to 1024 ints (v row offsets)
#define SMEM_STAGE0 9216     // 1024-aligned
#define XPANEL      16384    // 128 rows * 128B swizzled K-panel
#define VOFF        32768    // v tile offset inside a stage
#define VPANEL      8192     // 64 rows * 128B swizzled K-panel
#define STAGE_BYTES 49152    // 32KB x + 16KB v
#define SMEM_TOTAL  (SMEM_STAGE0 + 2 * STAGE_BYTES)   // 107520; 2 CTAs/SM

// ---------------------------------------------------------------------------
// Static device scratch (allocation-free rule: __device__ globals)
// ---------------------------------------------------------------------------
__device__ __align__(16) float g_xr[(size_t)TOKENS * KDIM];   // tf32-rounded x
__device__ __align__(16) float g_vr[(size_t)NB * 64 * 64];    // tf32-rounded values
__device__ int g_row_start[NROW + 1];
__device__ int g_row_blocks[NB];

// ---------------------------------------------------------------------------
// PTX helpers (compute_103 baseline features ONLY — no tcgen05 / 'a' features)
// ---------------------------------------------------------------------------
__device__ __forceinline__ uint32_t smem_u32(const void* p) {
    uint32_t a;
    asm("{ .reg .u64 t; cvta.to.shared.u64 t, %1; cvt.u32.u64 %0, t; }" : "=r"(a) : "l"(p));
    return a;
}

#define MBARRIER_INIT(a, c) \
    asm volatile("mbarrier.init.shared.b64 [%0], %1;" :: "r"((uint32_t)(a)), "r"((uint32_t)(c)) : "memory")
#define MBARRIER_INVAL(a) \
    asm volatile("mbarrier.inval.shared.b64 [%0];" :: "r"((uint32_t)(a)) : "memory")
#define MBARRIER_EXPECT_TX(a, tx) \
    asm volatile("mbarrier.arrive.expect_tx.shared.b64 _, [%0], %1;" \
                 :: "r"((uint32_t)(a)), "r"((uint32_t)(tx)) : "memory")

#define MBARRIER_WAIT_PARITY(mbar_smem_addr, phase_parity) do { \
    uint32_t _mbar = (uint32_t)(mbar_smem_addr); \
    uint32_t _parity = (uint32_t)(phase_parity); \
    uint32_t _done; \
    asm volatile( \
        "{\n\t.reg .pred p;\n\t" \
        "mbarrier.try_wait.parity.acquire.cta.shared::cta.b64 p, [%1], %2;\n\t" \
        "selp.b32 %0, 1, 0, p;\n\t}" \
        : "=r"(_done) : "r"(_mbar), "r"(_parity) : "memory"); \
    if (!_done) { \
        asm volatile( \
            "{\n\t.reg .pred P1;\n\t" \
            "WAIT_LOOP_%=:\n\t" \
            "mbarrier.try_wait.parity.acquire.cta.shared::cta.b64 P1, [%0], %1, 0x989680;\n\t" \
            "@P1 bra.uni WAIT_DONE_%=;\n\t" \
            "bra.uni WAIT_LOOP_%=;\n\t" \
            "WAIT_DONE_%=:\n\t}" \
            :: "r"(_mbar), "r"(_parity) : "memory"); \
    } \
} while (0)

#define TMA_LOAD_2D(dst, map, cx, cy, mbar) \
    asm volatile( \
        "cp.async.bulk.tensor.2d.shared::cta.global.tile.mbarrier::complete_tx::bytes " \
        "[%0], [%1, {%2, %3}], [%4];" \
        :: "r"((uint32_t)(dst)), "l"(map), "r"((int)(cx)), "r"((int)(cy)), \
           "r"((uint32_t)(mbar)) : "memory")

#define LDSM4(r0, r1, r2, r3, addr) \
    asm volatile("ldmatrix.sync.aligned.m8n8.x4.shared.b16 {%0,%1,%2,%3}, [%4];" \
                 : "=r"(r0), "=r"(r1), "=r"(r2), "=r"(r3) : "r"(addr))

__device__ __forceinline__ void mma_tf32(float* c, const uint32_t* a, uint32_t b0, uint32_t b1) {
    asm volatile(
        "mma.sync.aligned.m16n8k8.row.col.f32.tf32.tf32.f32 "
        "{%0,%1,%2,%3}, {%4,%5,%6,%7}, {%8,%9}, {%0,%1,%2,%3};"
        : "+f"(c[0]), "+f"(c[1]), "+f"(c[2]), "+f"(c[3])
        : "r"(a[0]), "r"(a[1]), "r"(a[2]), "r"(a[3]), "r"(b0), "r"(b1));
}

__device__ __forceinline__ float to_tf32(float x) {
    uint32_t u;
    asm("cvt.rna.tf32.f32 %0, %1;" : "=r"(u) : "f"(x));
    return __uint_as_float(u);
}

__device__ __forceinline__ float gelu_tanh(float v) {
    float inner = 0.7978845608f * (v + 0.044715f * v * v * v);
    float t;
    asm("tanh.approx.f32 %0, %1;" : "=f"(t) : "f"(inner));
    return 0.5f * v * (1.0f + t);
}

// ---------------------------------------------------------------------------
// Preprocess: tf32-round x and values into scratch (fused, one DRAM stream).
// rna rounding is load-bearing: mma.sync tf32 truncates operands (coherent
// ~1e-3 shrink); rna pre-rounding is zero-mean (~3e-4 final error).
// ---------------------------------------------------------------------------
__global__ void round_all_kernel(const float4* __restrict__ xs,
                                 const float4* __restrict__ vs) {
    const int n4x = TOKENS * KDIM / 4;
    const int n4v = NB * 64 * 64 / 4;
    float4* dx = reinterpret_cast<float4*>(g_xr);
    float4* dv = reinterpret_cast<float4*>(g_vr);
    int i  = blockIdx.x * blockDim.x + threadIdx.x;
    int st = gridDim.x * blockDim.x;
    for (; i < n4x + n4v; i += st) {
        if (i < n4x) {
            float4 t = xs[i];
            t.x = to_tf32(t.x); t.y = to_tf32(t.y); t.z = to_tf32(t.z); t.w = to_tf32(t.w);
            dx[i] = t;
        } else {
            int j = i - n4x;
            float4 t = vs[j];
            t.x = to_tf32(t.x); t.y = to_tf32(t.y); t.z = to_tf32(t.z); t.w = to_tf32(t.w);
            dv[j] = t;
        }
    }
}

// ---------------------------------------------------------------------------
// Preprocess: deterministic row-grouping of the 1024 blocks (stable order).
// ---------------------------------------------------------------------------
__global__ void build_lists_kernel(const int* __restrict__ brow) {
    __shared__ int whist[32 * NROW];
    __shared__ int wcum[32 * NROW];
    __shared__ int start_s[NROW];
    int tid = threadIdx.x;
    int w = tid >> 5, lane = tid & 31;

    whist[tid] = 0;
    whist[tid + 1024] = 0;
    __syncthreads();

    int r = brow[tid];
    unsigned grp = __match_any_sync(0xffffffffu, r);
    int rank_in  = __popc(grp & ((1u << lane) - 1u));
    int leader   = __ffs(grp) - 1;
    if (lane == leader) whist[w * NROW + r] = __popc(grp);
    __syncthreads();

    if (tid < NROW) {
        int s = 0;
        for (int ww = 0; ww < 32; ww++) {
            wcum[ww * NROW + tid] = s;
            s += whist[ww * NROW + tid];
        }
        start_s[tid] = s;
    }
    __syncthreads();
    if (tid == 0) {
        int s = 0;
        for (int i = 0; i < NROW; i++) {
            int c = start_s[i];
            start_s[i] = s;
            g_row_start[i] = s;
            s += c;
        }
        g_row_start[NROW] = s;
    }
    __syncthreads();

    g_row_blocks[start_s[r] + wcum[w * NROW + r] + rank_in] = tid;
}

// ---------------------------------------------------------------------------
// Main kernel: per (128-token tile, row-block). TMA 2-stage pipeline feeds
// SW128 SMEM; 8 warps (4 token x 2 out groups, 32x32 warp tiles) run
// ldmatrix.x4 + mma.sync m16n8k8 tf32 with register accumulators.
// ---------------------------------------------------------------------------
__device__ __forceinline__ void issue_load(uint32_t sb, int s, int c0, int vr0, int trow0,
                                           const CUtensorMap* tx, const CUtensorMap* tv) {
    uint32_t fullb = sb + (s ? MB_FULL1 : MB_FULL0);
    uint32_t xb = sb + SMEM_STAGE0 + s * STAGE_BYTES;
    MBARRIER_EXPECT_TX(fullb, STAGE_BYTES);
    TMA_LOAD_2D(xb,                 tx, c0,      trow0, fullb);   // x K 0..31
    TMA_LOAD_2D(xb + XPANEL,        tx, c0 + 32, trow0, fullb);   // x K 32..63
    TMA_LOAD_2D(xb + VOFF,          tv, 0,       vr0,   fullb);   // v K 0..31
    TMA_LOAD_2D(xb + VOFF + VPANEL, tv, 32,      vr0,   fullb);   // v K 32..63
}

__global__ __launch_bounds__(NTHREADS, 2)
void fsl_kernel(const __grid_constant__ CUtensorMap tmx,
                const __grid_constant__ CUtensorMap tmv,
                const int* __restrict__ bcol_g, const float* __restrict__ bias,
                float* __restrict__ y) {
    extern __shared__ char smem[];
    uint32_t sb = smem_u32(smem);
    int tid = threadIdx.x, wid = tid >> 5, lane = tid & 31;
    int tile = blockIdx.x;   // token tile 0..15
    int rb   = blockIdx.y;   // row block 0..63
    int tg = wid >> 1;       // token group 0..3 (32 tokens)
    int ng = wid & 1;        // out group 0..1 (32 outs)

    int bstart = g_row_start[rb];
    int nb     = g_row_start[rb + 1] - bstart;

    if (tid == 0) {
        MBARRIER_INIT(sb + MB_FULL0, 1);
        MBARRIER_INIT(sb + MB_FULL1, 1);
        asm volatile("prefetch.tensormap [%0];" :: "l"(&tmx));
        asm volatile("prefetch.tensormap [%0];" :: "l"(&tmv));
    }
    if (tid < 64) ((float*)(smem + SMEM_BIAS))[tid] = bias[rb * 64 + tid];
    int* scols = (int*)(smem + SMEM_COLS);
    int* sblk  = (int*)(smem + SMEM_BLK);
    for (int i = tid; i < nb; i += NTHREADS) {
        int b = g_row_blocks[bstart + i];
        scols[i] = bcol_g[b] * 64;
        sblk[i]  = b * 64;
    }
    __syncthreads();

    float acc[2][4][4];
#pragma unroll
    for (int a = 0; a < 2; a++)
#pragma unroll
        for (int b = 0; b < 4; b++)
#pragma unroll
            for (int c = 0; c < 4; c++) acc[a][b][c] = 0.0f;

    if (nb > 0) {
        if (tid == 0) {
            int trow0 = tile * MT;
            issue_load(sb, 0, scols[0], sblk[0], trow0, &tmx, &tmv);
            if (nb > 1) issue_load(sb, 1, scols[1], sblk[1], trow0, &tmx, &tmv);
        }

        // --- per-lane fragment address bases (fixed across iterations) ---
        // A (x): ldmatrix.x4 quadrants: lanes 0-7 rows+0/k+0, 8-15 rows+8/k+0,
        //        16-23 rows+0/k+4, 24-31 rows+8/k+4  (tf32 m16n8k8 A map)
        int arow0 = tg * 32 + (lane & 7) + ((lane >> 3) & 1) * 8;   // mt=0
        int kaddA = ((lane >> 4) & 1) * 4;
        uint32_t aoff0 = arow0 * 128, aoff1 = (arow0 + 16) * 128;
        uint32_t xra   = (uint32_t)((arow0 & 7) << 4);              // same for both mt
        // B (v): lanes 0-7 b0(nt even), 8-15 b1(nt even), 16-23 b0(nt odd), 24-31 b1(nt odd)
        int brow0 = (ng * 32) + (((lane >> 4) & 1) + 0) * 8 + (lane & 7);   // np=0
        int kaddB = ((lane >> 3) & 1) * 4;
        uint32_t boff0 = brow0 * 128, boff1 = (brow0 + 16) * 128;   // np=1: nt += 2
        uint32_t xrb   = (uint32_t)((brow0 & 7) << 4);              // same for both np

        uint32_t pf0 = 0, pf1 = 0;
        for (int it = 0; it < nb; it++) {
            int s = it & 1;
            if (s == 0) { MBARRIER_WAIT_PARITY(sb + MB_FULL0, pf0); pf0 ^= 1; }
            else        { MBARRIER_WAIT_PARITY(sb + MB_FULL1, pf1); pf1 ^= 1; }

            uint32_t xb = sb + SMEM_STAGE0 + s * STAGE_BYTES;
            uint32_t vb = xb + VOFF;
#pragma unroll
            for (int kk = 0; kk < 8; kk++) {
                uint32_t pA = xb + (kk >> 2) * XPANEL;
                uint32_t pB = vb + (kk >> 2) * VPANEL;
                uint32_t kp = (kk & 3) * 8;
                uint32_t a0[4], a1[4], b0[4], b1[4];
                uint32_t kA = ((kp + kaddA) << 2) ^ xra;
                uint32_t kB = ((kp + kaddB) << 2) ^ xrb;
                LDSM4(a0[0], a0[1], a0[2], a0[3], pA + aoff0 + kA);
                LDSM4(a1[0], a1[1], a1[2], a1[3], pA + aoff1 + kA);
                LDSM4(b0[0], b0[1], b0[2], b0[3], pB + boff0 + kB);
                LDSM4(b1[0], b1[1], b1[2], b1[3], pB + boff1 + kB);
                mma_tf32(acc[0][0], a0, b0[0], b0[1]);
                mma_tf32(acc[0][1], a0, b0[2], b0[3]);
                mma_tf32(acc[0][2], a0, b1[0], b1[1]);
                mma_tf32(acc[0][3], a0, b1[2], b1[3]);
                mma_tf32(acc[1][0], a1, b0[0], b0[1]);
                mma_tf32(acc[1][1], a1, b0[2], b0[3]);
                mma_tf32(acc[1][2], a1, b1[0], b1[1]);
                mma_tf32(acc[1][3], a1, b1[2], b1[3]);
            }
            __syncthreads();   // all warps done reading stage s
            if (it + 2 < nb && tid == 0)
                issue_load(sb, s, scols[it + 2], sblk[it + 2], tile * MT, &tmx, &tmv);
        }
    }

    // ---------------- epilogue: bias + gelu + store ----------------
    const float* bs = (const float*)(smem + SMEM_BIAS);
#pragma unroll
    for (int mt = 0; mt < 2; mt++) {
#pragma unroll
        for (int nt = 0; nt < 4; nt++) {
            int row = tile * MT + tg * 32 + mt * 16 + (lane >> 2);
            int colL = ng * 32 + nt * 8 + (lane & 3) * 2;
            float bb0 = bs[colL], bb1 = bs[colL + 1];
            float* p0 = y + (size_t)row * MDIM + rb * 64 + colL;
            float* p1 = p0 + (size_t)8 * MDIM;
            float2 o0, o1;
            o0.x = gelu_tanh(acc[mt][nt][0] + bb0);
            o0.y = gelu_tanh(acc[mt][nt][1] + bb1);
            o1.x = gelu_tanh(acc[mt][nt][2] + bb0);
            o1.y = gelu_tanh(acc[mt][nt][3] + bb1);
            *reinterpret_cast<float2*>(p0) = o0;
            *reinterpret_cast<float2*>(p1) = o1;
        }
    }

    __syncthreads();
    if (tid == 0) {
        MBARRIER_INVAL(sb + MB_FULL0);
        MBARRIER_INVAL(sb + MB_FULL1);
    }
}

// ---------------------------------------------------------------------------
// Launch (host).
// ---------------------------------------------------------------------------
typedef CUresult (CUDAAPI *PFN_tmap_encode_t)(
    CUtensorMap*, CUtensorMapDataType, cuuint32_t, void*,
    const cuuint64_t*, const cuuint64_t*, const cuuint32_t*, const cuuint32_t*,
    CUtensorMapInterleave, CUtensorMapSwizzle, CUtensorMapL2promotion,
    CUtensorMapFloatOOBfill);

extern "C" void kernel_launch(void* const* d_in, const int* in_sizes, int n_in,
                              void* d_out, int out_size) {
    const float* x      = (const float*)d_in[0];
    const float* values = (const float*)d_in[1];
    const float* bias   = (const float*)d_in[2];
    const int*   brow   = (const int*)d_in[3];
    const int*   bcol   = (const int*)d_in[4];
    float*       y      = (float*)d_out;

    void* fn = nullptr;
    cudaDriverEntryPointQueryResult qr;
    cudaGetDriverEntryPoint("cuTensorMapEncodeTiled", &fn, cudaEnableDefault, &qr);
    PFN_tmap_encode_t enc = (PFN_tmap_encode_t)fn;

    void* xr_ptr = nullptr;
    void* vr_ptr = nullptr;
    cudaGetSymbolAddress(&xr_ptr, g_xr);
    cudaGetSymbolAddress(&vr_ptr, g_vr);

    alignas(64) CUtensorMap tmx;
    alignas(64) CUtensorMap tmv;
    {
        cuuint64_t dims[2]    = {KDIM, TOKENS};
        cuuint64_t strides[1] = {KDIM * sizeof(float)};
        cuuint32_t box[2]     = {32, MT};           // 128B inner (SW128)
        cuuint32_t es[2]      = {1, 1};
        enc(&tmx, CU_TENSOR_MAP_DATA_TYPE_FLOAT32, 2, xr_ptr, dims, strides, box, es,
            CU_TENSOR_MAP_INTERLEAVE_NONE, CU_TENSOR_MAP_SWIZZLE_128B,
            CU_TENSOR_MAP_L2_PROMOTION_L2_256B, CU_TENSOR_MAP_FLOAT_OOB_FILL_NONE);
    }
    {
        cuuint64_t dims[2]    = {64, (cuuint64_t)NB * 64};
        cuuint64_t strides[1] = {64 * sizeof(float)};
        cuuint32_t box[2]     = {32, 64};
        cuuint32_t es[2]      = {1, 1};
        enc(&tmv, CU_TENSOR_MAP_DATA_TYPE_FLOAT32, 2, vr_ptr, dims, strides, box, es,
            CU_TENSOR_MAP_INTERLEAVE_NONE, CU_TENSOR_MAP_SWIZZLE_128B,
            CU_TENSOR_MAP_L2_PROMOTION_L2_256B, CU_TENSOR_MAP_FLOAT_OOB_FILL_NONE);
    }

    cudaFuncSetAttribute(fsl_kernel, cudaFuncAttributeMaxDynamicSharedMemorySize, SMEM_TOTAL);

    build_lists_kernel<<<1, NB>>>(brow);
    round_all_kernel<<<592, 256>>>((const float4*)x, (const float4*)values);

    dim3 grid(NTILE, NROW);
    fsl_kernel<<<grid, NTHREADS, SMEM_TOTAL>>>(tmx, tmv, bcol, bias, y);
}

// round 13
// speedup vs baseline: 1.0632x; 1.0632x over previous
#include <cuda_runtime.h>
#include <cuda.h>
#include <cstdint>

// ---------------------------------------------------------------------------
// Problem constants (shapes fixed by the dataset)
// ---------------------------------------------------------------------------
#define TOKENS   2048
#define KDIM     4096
#define MDIM     4096
#define NB       1024
#define NROW     64          // MDIM / 64
#define MT       128         // token tile
#define NTILE    (TOKENS / MT)   // 16
#define NTHREADS 256         // 8 warps: 4 token-groups x 2 out-groups
#define RA_BLOCKS 592        // rounding blocks (one extra block builds lists)

// SMEM map (header + 4 half-block stages)
#define MB_FULL     8        // 4 x 8B mbarriers at 8,16,24,32
#define SMEM_BIAS   64       // 64 floats
#define SMEM_COLS   512      // up to 1024 ints (col offsets, elements)
#define SMEM_BLK    4608     // up to 1024 ints (v row offsets)
#define SMEM_STAGE0 9216     // 1024-aligned
#define HVOFF       16384    // v panel offset inside a half-stage
#define HSTAGE_BYTES 24576   // 16KB x panel + 8KB v panel
#define SMEM_TOTAL  (SMEM_STAGE0 + 4 * HSTAGE_BYTES)   // 107520; 2 CTAs/SM

// ---------------------------------------------------------------------------
// Static device scratch (allocation-free rule: __device__ globals)
// ---------------------------------------------------------------------------
__device__ __align__(16) float g_xr[(size_t)TOKENS * KDIM];   // tf32-rounded x
__device__ __align__(16) float g_vr[(size_t)NB * 64 * 64];    // tf32-rounded values
__device__ int g_row_start[NROW + 1];
__device__ int g_row_blocks[NB];
__device__ int g_row_order[NROW];     // rows sorted by descending block count (LPT)

// ---------------------------------------------------------------------------
// PTX helpers (compute_103 baseline features ONLY — no tcgen05 / 'a' features)
// ---------------------------------------------------------------------------
__device__ __forceinline__ uint32_t smem_u32(const void* p) {
    uint32_t a;
    asm("{ .reg .u64 t; cvta.to.shared.u64 t, %1; cvt.u32.u64 %0, t; }" : "=r"(a) : "l"(p));
    return a;
}

#define MBARRIER_INIT(a, c) \
    asm volatile("mbarrier.init.shared.b64 [%0], %1;" :: "r"((uint32_t)(a)), "r"((uint32_t)(c)) : "memory")
#define MBARRIER_INVAL(a) \
    asm volatile("mbarrier.inval.shared.b64 [%0];" :: "r"((uint32_t)(a)) : "memory")
#define MBARRIER_EXPECT_TX(a, tx) \
    asm volatile("mbarrier.arrive.expect_tx.shared.b64 _, [%0], %1;" \
                 :: "r"((uint32_t)(a)), "r"((uint32_t)(tx)) : "memory")

#define MBARRIER_WAIT_PARITY(mbar_smem_addr, phase_parity) do { \
    uint32_t _mbar = (uint32_t)(mbar_smem_addr); \
    uint32_t _parity = (uint32_t)(phase_parity); \
    uint32_t _done; \
    asm volatile( \
        "{\n\t.reg .pred p;\n\t" \
        "mbarrier.try_wait.parity.acquire.cta.shared::cta.b64 p, [%1], %2;\n\t" \
        "selp.b32 %0, 1, 0, p;\n\t}" \
        : "=r"(_done) : "r"(_mbar), "r"(_parity) : "memory"); \
    if (!_done) { \
        asm volatile( \
            "{\n\t.reg .pred P1;\n\t" \
            "WAIT_LOOP_%=:\n\t" \
            "mbarrier.try_wait.parity.acquire.cta.shared::cta.b64 P1, [%0], %1, 0x989680;\n\t" \
            "@P1 bra.uni WAIT_DONE_%=;\n\t" \
            "bra.uni WAIT_LOOP_%=;\n\t" \
            "WAIT_DONE_%=:\n\t}" \
            :: "r"(_mbar), "r"(_parity) : "memory"); \
    } \
} while (0)

#define TMA_LOAD_2D(dst, map, cx, cy, mbar) \
    asm volatile( \
        "cp.async.bulk.tensor.2d.shared::cta.global.tile.mbarrier::complete_tx::bytes " \
        "[%0], [%1, {%2, %3}], [%4];" \
        :: "r"((uint32_t)(dst)), "l"(map), "r"((int)(cx)), "r"((int)(cy)), \
           "r"((uint32_t)(mbar)) : "memory")

#define LDSM4(r0, r1, r2, r3, addr) \
    asm volatile("ldmatrix.sync.aligned.m8n8.x4.shared.b16 {%0,%1,%2,%3}, [%4];" \
                 : "=r"(r0), "=r"(r1), "=r"(r2), "=r"(r3) : "r"(addr))

__device__ __forceinline__ void mma_tf32(float* c, const uint32_t* a, uint32_t b0, uint32_t b1) {
    asm volatile(
        "mma.sync.aligned.m16n8k8.row.col.f32.tf32.tf32.f32 "
        "{%0,%1,%2,%3}, {%4,%5,%6,%7}, {%8,%9}, {%0,%1,%2,%3};"
        : "+f"(c[0]), "+f"(c[1]), "+f"(c[2]), "+f"(c[3])
        : "r"(a[0]), "r"(a[1]), "r"(a[2]), "r"(a[3]), "r"(b0), "r"(b1));
}

__device__ __forceinline__ float to_tf32(float x) {
    uint32_t u;
    asm("cvt.rna.tf32.f32 %0, %1;" : "=r"(u) : "f"(x));
    return __uint_as_float(u);
}

__device__ __forceinline__ float gelu_tanh(float v) {
    float inner = 0.7978845608f * (v + 0.044715f * v * v * v);
    float t;
    asm("tanh.approx.f32 %0, %1;" : "=f"(t) : "f"(inner));
    return 0.5f * v * (1.0f + t);
}

// ---------------------------------------------------------------------------
// Preprocess (single kernel): blocks 0..591 tf32-round x and values (DRAM
// stream, ~16us); block 592 builds the row lists + LPT order (~3us, hidden).
// rna rounding is load-bearing: truncation would bias ~1e-3; rna is zero-mean.
// ---------------------------------------------------------------------------
__global__ void preprocess_kernel(const float4* __restrict__ xs,
                                  const float4* __restrict__ vs,
                                  const int* __restrict__ brow) {
    if (blockIdx.x == RA_BLOCKS) {
        // ---- list builder (deterministic, stable by block index) ----
        __shared__ int sbr[NB];
        __shared__ int cnt_s[NROW];
        __shared__ int start_sh[NROW];
        int tid = threadIdx.x;
        for (int i = tid; i < NB; i += NTHREADS) sbr[i] = brow[i];
        __syncthreads();
        if (tid < NROW) {
            int c = 0;
            for (int i = 0; i < NB; i++) c += (sbr[i] == tid);
            cnt_s[tid] = c;
        }
        __syncthreads();
        if (tid == 0) {
            int s = 0;
            for (int r = 0; r < NROW; r++) {
                start_sh[r] = s;
                g_row_start[r] = s;
                s += cnt_s[r];
            }
            g_row_start[NROW] = s;
        }
        __syncthreads();
        if (tid < NROW) {
            // stable fill: scan blocks in index order
            int k = start_sh[tid];
            for (int i = 0; i < NB; i++)
                if (sbr[i] == tid) g_row_blocks[k++] = i;
            // LPT rank: rows with more blocks first; ties by row index
            int myc = cnt_s[tid];
            int rank = 0;
            for (int r = 0; r < NROW; r++) {
                int c = cnt_s[r];
                rank += (c > myc) || (c == myc && r < tid);
            }
            g_row_order[rank] = tid;
        }
        return;
    }

    // ---- tf32 rounding stream ----
    const int n4x = TOKENS * KDIM / 4;
    const int n4v = NB * 64 * 64 / 4;
    float4* dx = reinterpret_cast<float4*>(g_xr);
    float4* dv = reinterpret_cast<float4*>(g_vr);
    int i  = blockIdx.x * blockDim.x + threadIdx.x;
    int st = RA_BLOCKS * blockDim.x;
    for (; i < n4x + n4v; i += st) {
        if (i < n4x) {
            float4 t = xs[i];
            t.x = to_tf32(t.x); t.y = to_tf32(t.y); t.z = to_tf32(t.z); t.w = to_tf32(t.w);
            dx[i] = t;
        } else {
            int j = i - n4x;
            float4 t = vs[j];
            t.x = to_tf32(t.x); t.y = to_tf32(t.y); t.z = to_tf32(t.z); t.w = to_tf32(t.w);
            dv[j] = t;
        }
    }
}

// ---------------------------------------------------------------------------
// Main kernel: per (128-token tile, row-block). TMA 4x24KB half-stage pipeline
// (lead 4 half-iters kills the 2-stage bubble); 8 warps (4 token x 2 out
// groups, 32x32 warp tiles) run ldmatrix.x4 + mma.sync m16n8k8 tf32.
// ---------------------------------------------------------------------------
__device__ __forceinline__ void issue_half(uint32_t sb, int h, const int* scols,
                                           const int* sblk, int trow0,
                                           const CUtensorMap* tx, const CUtensorMap* tv) {
    int stage = h & 3, blk = h >> 1, half = h & 1;
    uint32_t fullb = sb + MB_FULL + stage * 8;
    uint32_t base  = sb + SMEM_STAGE0 + stage * HSTAGE_BYTES;
    MBARRIER_EXPECT_TX(fullb, HSTAGE_BYTES);
    TMA_LOAD_2D(base,         tx, scols[blk] + 32 * half, trow0,     fullb);  // x panel
    TMA_LOAD_2D(base + HVOFF, tv, 32 * half,              sblk[blk], fullb);  // v panel
}

__global__ __launch_bounds__(NTHREADS, 2)
void fsl_kernel(const __grid_constant__ CUtensorMap tmx,
                const __grid_constant__ CUtensorMap tmv,
                const int* __restrict__ bcol_g, const float* __restrict__ bias,
                float* __restrict__ y) {
    extern __shared__ char smem[];
    uint32_t sb = smem_u32(smem);
    int tid = threadIdx.x, wid = tid >> 5, lane = tid & 31;
    int tile = blockIdx.x;                 // token tile 0..15
    int rb   = g_row_order[blockIdx.y];    // LPT: heavy rows scheduled first
    int tg = wid >> 1;       // token group 0..3 (32 tokens)
    int ng = wid & 1;        // out group 0..1 (32 outs)

    int bstart = g_row_start[rb];
    int nb     = g_row_start[rb + 1] - bstart;

    if (tid == 0) {
#pragma unroll
        for (int s = 0; s < 4; s++) MBARRIER_INIT(sb + MB_FULL + s * 8, 1);
        asm volatile("prefetch.tensormap [%0];" :: "l"(&tmx));
        asm volatile("prefetch.tensormap [%0];" :: "l"(&tmv));
    }
    if (tid < 64) ((float*)(smem + SMEM_BIAS))[tid] = bias[rb * 64 + tid];
    int* scols = (int*)(smem + SMEM_COLS);
    int* sblk  = (int*)(smem + SMEM_BLK);
    for (int i = tid; i < nb; i += NTHREADS) {
        int b = g_row_blocks[bstart + i];
        scols[i] = bcol_g[b] * 64;
        sblk[i]  = b * 64;
    }
    __syncthreads();

    float acc[2][4][4];
#pragma unroll
    for (int a = 0; a < 2; a++)
#pragma unroll
        for (int b = 0; b < 4; b++)
#pragma unroll
            for (int c = 0; c < 4; c++) acc[a][b][c] = 0.0f;

    if (nb > 0) {
        int nh = nb * 2;
        int trow0 = tile * MT;
        if (tid == 0) {
#pragma unroll
            for (int h = 0; h < 4; h++)
                if (h < nh) issue_half(sb, h, scols, sblk, trow0, &tmx, &tmv);
        }

        // --- per-lane fragment address bases (fixed across iterations) ---
        // A (x): ldmatrix.x4 quadrants: lanes 0-7 rows+0/k+0, 8-15 rows+8/k+0,
        //        16-23 rows+0/k+4, 24-31 rows+8/k+4  (tf32 m16n8k8 A map)
        int arow0 = tg * 32 + (lane & 7) + ((lane >> 3) & 1) * 8;   // mt=0
        int kaddA = ((lane >> 4) & 1) * 4;
        uint32_t aoff0 = arow0 * 128, aoff1 = (arow0 + 16) * 128;
        uint32_t xra   = (uint32_t)((arow0 & 7) << 4);
        // B (v): lanes 0-7 b0(nt even), 8-15 b1(nt even), 16-23 b0(nt odd), 24-31 b1(nt odd)
        int brow0 = (ng * 32) + ((lane >> 4) & 1) * 8 + (lane & 7);  // np=0
        int kaddB = ((lane >> 3) & 1) * 4;
        uint32_t boff0 = brow0 * 128, boff1 = (brow0 + 16) * 128;
        uint32_t xrb   = (uint32_t)((brow0 & 7) << 4);

        for (int h = 0; h < nh; h++) {
            MBARRIER_WAIT_PARITY(sb + MB_FULL + (h & 3) * 8, (h >> 2) & 1);

            uint32_t pA = sb + SMEM_STAGE0 + (h & 3) * HSTAGE_BYTES;
            uint32_t pB = pA + HVOFF;
#pragma unroll
            for (int kk = 0; kk < 4; kk++) {
                uint32_t kp = kk * 8;
                uint32_t a0[4], a1[4], b0[4], b1[4];
                uint32_t kA = ((kp + kaddA) << 2) ^ xra;
                uint32_t kB = ((kp + kaddB) << 2) ^ xrb;
                LDSM4(a0[0], a0[1], a0[2], a0[3], pA + aoff0 + kA);
                LDSM4(a1[0], a1[1], a1[2], a1[3], pA + aoff1 + kA);
                LDSM4(b0[0], b0[1], b0[2], b0[3], pB + boff0 + kB);
                LDSM4(b1[0], b1[1], b1[2], b1[3], pB + boff1 + kB);
                mma_tf32(acc[0][0], a0, b0[0], b0[1]);
                mma_tf32(acc[0][1], a0, b0[2], b0[3]);
                mma_tf32(acc[0][2], a0, b1[0], b1[1]);
                mma_tf32(acc[0][3], a0, b1[2], b1[3]);
                mma_tf32(acc[1][0], a1, b0[0], b0[1]);
                mma_tf32(acc[1][1], a1, b0[2], b0[3]);
                mma_tf32(acc[1][2], a1, b1[0], b1[1]);
                mma_tf32(acc[1][3], a1, b1[2], b1[3]);
            }
            __syncthreads();   // all warps done reading stage h&3
            if (h + 4 < nh && tid == 0)
                issue_half(sb, h + 4, scols, sblk, trow0, &tmx, &tmv);
        }
    }

    // ---------------- epilogue: bias + gelu + store ----------------
    const float* bs = (const float*)(smem + SMEM_BIAS);
#pragma unroll
    for (int mt = 0; mt < 2; mt++) {
#pragma unroll
        for (int nt = 0; nt < 4; nt++) {
            int row = tile * MT + tg * 32 + mt * 16 + (lane >> 2);
            int colL = ng * 32 + nt * 8 + (lane & 3) * 2;
            float bb0 = bs[colL], bb1 = bs[colL + 1];
            float* p0 = y + (size_t)row * MDIM + rb * 64 + colL;
            float* p1 = p0 + (size_t)8 * MDIM;
            float2 o0, o1;
            o0.x = gelu_tanh(acc[mt][nt][0] + bb0);
            o0.y = gelu_tanh(acc[mt][nt][1] + bb1);
            o1.x = gelu_tanh(acc[mt][nt][2] + bb0);
            o1.y = gelu_tanh(acc[mt][nt][3] + bb1);
            *reinterpret_cast<float2*>(p0) = o0;
            *reinterpret_cast<float2*>(p1) = o1;
        }
    }

    __syncthreads();
    if (tid == 0) {
#pragma unroll
        for (int s = 0; s < 4; s++) MBARRIER_INVAL(sb + MB_FULL + s * 8);
    }
}

// ---------------------------------------------------------------------------
// Launch (host).
// ---------------------------------------------------------------------------
typedef CUresult (CUDAAPI *PFN_tmap_encode_t)(
    CUtensorMap*, CUtensorMapDataType, cuuint32_t, void*,
    const cuuint64_t*, const cuuint64_t*, const cuuint32_t*, const cuuint32_t*,
    CUtensorMapInterleave, CUtensorMapSwizzle, CUtensorMapL2promotion,
    CUtensorMapFloatOOBfill);

extern "C" void kernel_launch(void* const* d_in, const int* in_sizes, int n_in,
                              void* d_out, int out_size) {
    const float* x      = (const float*)d_in[0];
    const float* values = (const float*)d_in[1];
    const float* bias   = (const float*)d_in[2];
    const int*   brow   = (const int*)d_in[3];
    const int*   bcol   = (const int*)d_in[4];
    float*       y      = (float*)d_out;

    void* fn = nullptr;
    cudaDriverEntryPointQueryResult qr;
    cudaGetDriverEntryPoint("cuTensorMapEncodeTiled", &fn, cudaEnableDefault, &qr);
    PFN_tmap_encode_t enc = (PFN_tmap_encode_t)fn;

    void* xr_ptr = nullptr;
    void* vr_ptr = nullptr;
    cudaGetSymbolAddress(&xr_ptr, g_xr);
    cudaGetSymbolAddress(&vr_ptr, g_vr);

    alignas(64) CUtensorMap tmx;
    alignas(64) CUtensorMap tmv;
    {
        cuuint64_t dims[2]    = {KDIM, TOKENS};
        cuuint64_t strides[1] = {KDIM * sizeof(float)};
        cuuint32_t box[2]     = {32, MT};           // 128B inner (SW128)
        cuuint32_t es[2]      = {1, 1};
        enc(&tmx, CU_TENSOR_MAP_DATA_TYPE_FLOAT32, 2, xr_ptr, dims, strides, box, es,
            CU_TENSOR_MAP_INTERLEAVE_NONE, CU_TENSOR_MAP_SWIZZLE_128B,
            CU_TENSOR_MAP_L2_PROMOTION_L2_256B, CU_TENSOR_MAP_FLOAT_OOB_FILL_NONE);
    }
    {
        cuuint64_t dims[2]    = {64, (cuuint64_t)NB * 64};
        cuuint64_t strides[1] = {64 * sizeof(float)};
        cuuint32_t box[2]     = {32, 64};
        cuuint32_t es[2]      = {1, 1};
        enc(&tmv, CU_TENSOR_MAP_DATA_TYPE_FLOAT32, 2, vr_ptr, dims, strides, box, es,
            CU_TENSOR_MAP_INTERLEAVE_NONE, CU_TENSOR_MAP_SWIZZLE_128B,
            CU_TENSOR_MAP_L2_PROMOTION_L2_256B, CU_TENSOR_MAP_FLOAT_OOB_FILL_NONE);
    }

    cudaFuncSetAttribute(fsl_kernel, cudaFuncAttributeMaxDynamicSharedMemorySize, SMEM_TOTAL);

    preprocess_kernel<<<RA_BLOCKS + 1, NTHREADS>>>((const float4*)x, (const float4*)values, brow);

    dim3 grid(NTILE, NROW);
    fsl_kernel<<<grid, NTHREADS, SMEM_TOTAL>>>(tmx, tmv, bcol, bias, y);
}

// round 14
// speedup vs baseline: 1.1948x; 1.1237x over previous
#include <cuda_runtime.h>
#include <cuda.h>
#include <cstdint>

// ---------------------------------------------------------------------------
// Problem constants (shapes fixed by the dataset)
// ---------------------------------------------------------------------------
#define TOKENS   2048
#define KDIM     4096
#define MDIM     4096
#define NB       1024
#define NROW     64          // MDIM / 64
#define MT       128         // token tile
#define NTILE    (TOKENS / MT)   // 16
#define NTHREADS 288         // 8 compute warps (4 token x 2 out) + 1 producer warp

// SMEM map (header + 4 half-block stages)
#define MB_FULL     8        // 4 x 8B full barriers at 8..39
#define MB_EMPTY    40       // 4 x 8B empty barriers at 40..71
#define SMEM_BIAS   128      // 64 floats
#define SMEM_COLS   512      // up to 1024 ints (col offsets, elements)
#define SMEM_BLK    4608     // up to 1024 ints (v row offsets)
#define SMEM_STAGE0 9216     // 1024-aligned
#define HVOFF       16384    // v panel offset inside a half-stage
#define HSTAGE_BYTES 24576   // 16KB x panel + 8KB v panel
#define SMEM_TOTAL  (SMEM_STAGE0 + 4 * HSTAGE_BYTES)   // 107520; 2 CTAs/SM

// ---------------------------------------------------------------------------
// Static device scratch (allocation-free rule: __device__ globals)
// ---------------------------------------------------------------------------
__device__ int g_row_start[NROW + 1];
__device__ int g_row_blocks[NB];
__device__ int g_row_order[NROW];     // rows sorted by descending block count (LPT)

// ---------------------------------------------------------------------------
// PTX helpers (compute_103 baseline features ONLY — no tcgen05 / 'a' features)
// ---------------------------------------------------------------------------
__device__ __forceinline__ uint32_t smem_u32(const void* p) {
    uint32_t a;
    asm("{ .reg .u64 t; cvta.to.shared.u64 t, %1; cvt.u32.u64 %0, t; }" : "=r"(a) : "l"(p));
    return a;
}

#define MBARRIER_INIT(a, c) \
    asm volatile("mbarrier.init.shared.b64 [%0], %1;" :: "r"((uint32_t)(a)), "r"((uint32_t)(c)) : "memory")
#define MBARRIER_INVAL(a) \
    asm volatile("mbarrier.inval.shared.b64 [%0];" :: "r"((uint32_t)(a)) : "memory")
#define MBARRIER_EXPECT_TX(a, tx) \
    asm volatile("mbarrier.arrive.expect_tx.shared.b64 _, [%0], %1;" \
                 :: "r"((uint32_t)(a)), "r"((uint32_t)(tx)) : "memory")
#define MBARRIER_ARRIVE(a) \
    asm volatile("mbarrier.arrive.shared.b64 _, [%0];" :: "r"((uint32_t)(a)) : "memory")

#define MBARRIER_WAIT_PARITY(mbar_smem_addr, phase_parity) do { \
    uint32_t _mbar = (uint32_t)(mbar_smem_addr); \
    uint32_t _parity = (uint32_t)(phase_parity); \
    uint32_t _done; \
    asm volatile( \
        "{\n\t.reg .pred p;\n\t" \
        "mbarrier.try_wait.parity.acquire.cta.shared::cta.b64 p, [%1], %2;\n\t" \
        "selp.b32 %0, 1, 0, p;\n\t}" \
        : "=r"(_done) : "r"(_mbar), "r"(_parity) : "memory"); \
    if (!_done) { \
        asm volatile( \
            "{\n\t.reg .pred P1;\n\t" \
            "WAIT_LOOP_%=:\n\t" \
            "mbarrier.try_wait.parity.acquire.cta.shared::cta.b64 P1, [%0], %1, 0x989680;\n\t" \
            "@P1 bra.uni WAIT_DONE_%=;\n\t" \
            "bra.uni WAIT_LOOP_%=;\n\t" \
            "WAIT_DONE_%=:\n\t}" \
            :: "r"(_mbar), "r"(_parity) : "memory"); \
    } \
} while (0)

#define TMA_LOAD_2D(dst, map, cx, cy, mbar) \
    asm volatile( \
        "cp.async.bulk.tensor.2d.shared::cta.global.tile.mbarrier::complete_tx::bytes " \
        "[%0], [%1, {%2, %3}], [%4];" \
        :: "r"((uint32_t)(dst)), "l"(map), "r"((int)(cx)), "r"((int)(cy)), \
           "r"((uint32_t)(mbar)) : "memory")

#define LDSM4(r0, r1, r2, r3, addr) \
    asm volatile("ldmatrix.sync.aligned.m8n8.x4.shared.b16 {%0,%1,%2,%3}, [%4];" \
                 : "=r"(r0), "=r"(r1), "=r"(r2), "=r"(r3) : "r"(addr))

__device__ __forceinline__ void mma_tf32(float* c, const uint32_t* a, uint32_t b0, uint32_t b1) {
    asm volatile(
        "mma.sync.aligned.m16n8k8.row.col.f32.tf32.tf32.f32 "
        "{%0,%1,%2,%3}, {%4,%5,%6,%7}, {%8,%9}, {%0,%1,%2,%3};"
        : "+f"(c[0]), "+f"(c[1]), "+f"(c[2]), "+f"(c[3])
        : "r"(a[0]), "r"(a[1]), "r"(a[2]), "r"(a[3]), "r"(b0), "r"(b1));
}

// In-register rna tf32 rounding (identical numerics to pre-rounded scratch:
// mma.sync's internal truncation is a no-op on already-rounded values).
__device__ __forceinline__ void round4(uint32_t* r) {
    asm("cvt.rna.tf32.f32 %0, %0;" : "+r"(r[0]));
    asm("cvt.rna.tf32.f32 %0, %0;" : "+r"(r[1]));
    asm("cvt.rna.tf32.f32 %0, %0;" : "+r"(r[2]));
    asm("cvt.rna.tf32.f32 %0, %0;" : "+r"(r[3]));
}

__device__ __forceinline__ float gelu_tanh(float v) {
    float inner = 0.7978845608f * (v + 0.044715f * v * v * v);
    float t;
    asm("tanh.approx.f32 %0, %1;" : "=f"(t) : "f"(inner));
    return 0.5f * v * (1.0f + t);
}

// ---------------------------------------------------------------------------
// Preprocess: deterministic row-grouping + LPT order (single tiny kernel).
// ---------------------------------------------------------------------------
__global__ void build_lists_kernel(const int* __restrict__ brow) {
    __shared__ int whist[32 * NROW];
    __shared__ int wcum[32 * NROW];
    __shared__ int cnts[NROW];
    __shared__ int starts[NROW];
    int tid = threadIdx.x;             // 1024 threads
    int w = tid >> 5, lane = tid & 31;

    whist[tid] = 0;
    whist[tid + 1024] = 0;
    __syncthreads();

    int r = brow[tid];
    unsigned grp = __match_any_sync(0xffffffffu, r);
    int rank_in  = __popc(grp & ((1u << lane) - 1u));
    int leader   = __ffs(grp) - 1;
    if (lane == leader) whist[w * NROW + r] = __popc(grp);
    __syncthreads();

    if (tid < NROW) {
        int s = 0;
        for (int ww = 0; ww < 32; ww++) {
            wcum[ww * NROW + tid] = s;
            s += whist[ww * NROW + tid];
        }
        cnts[tid] = s;
    }
    __syncthreads();
    if (tid == 0) {
        int s = 0;
        for (int i = 0; i < NROW; i++) {
            starts[i] = s;
            g_row_start[i] = s;
            s += cnts[i];
        }
        g_row_start[NROW] = s;
    }
    __syncthreads();

    g_row_blocks[starts[r] + wcum[w * NROW + r] + rank_in] = tid;

    if (tid < NROW) {
        // LPT rank: rows with more blocks first; ties by row index
        int myc = cnts[tid];
        int rank = 0;
        for (int r2 = 0; r2 < NROW; r2++) {
            int c = cnts[r2];
            rank += (c > myc) || (c == myc && r2 < tid);
        }
        g_row_order[rank] = tid;
    }
}

// ---------------------------------------------------------------------------
// Main kernel. 9 warps: warps 0-7 compute (4 token x 2 out groups, 32x32 warp
// tiles, ldmatrix.x4 + in-register rna-tf32 + mma.sync m16n8k8); warp 8 is a
// dedicated TMA producer against per-stage full/empty mbarriers. No
// __syncthreads in the mainloop. 4 x 24KB half-block stages.
// ---------------------------------------------------------------------------
__global__ void __launch_bounds__(NTHREADS, 2)
fsl_kernel(const __grid_constant__ CUtensorMap tmx,
           const __grid_constant__ CUtensorMap tmv,
           const int* __restrict__ bcol_g, const float* __restrict__ bias,
           float* __restrict__ y) {
    extern __shared__ char smem[];
    uint32_t sb = smem_u32(smem);
    int tid = threadIdx.x, wid = tid >> 5, lane = tid & 31;
    int tile = blockIdx.x;                 // token tile 0..15
    int rb   = g_row_order[blockIdx.y];    // LPT: heavy rows scheduled first
    int tg = wid >> 1;       // token group 0..3 (32 tokens) [compute warps]
    int ng = wid & 1;        // out group 0..1 (32 outs)

    int bstart = g_row_start[rb];
    int nb     = g_row_start[rb + 1] - bstart;
    int nh     = nb * 2;

    if (tid == 0) {
#pragma unroll
        for (int s = 0; s < 4; s++) {
            MBARRIER_INIT(sb + MB_FULL + s * 8, 1);    // tx-completed by producer
            MBARRIER_INIT(sb + MB_EMPTY + s * 8, 8);   // one arrive per compute warp
        }
        asm volatile("prefetch.tensormap [%0];" :: "l"(&tmx));
        asm volatile("prefetch.tensormap [%0];" :: "l"(&tmv));
    }
    if (tid < 64) ((float*)(smem + SMEM_BIAS))[tid] = bias[rb * 64 + tid];
    int* scols = (int*)(smem + SMEM_COLS);
    int* sblk  = (int*)(smem + SMEM_BLK);
    for (int i = tid; i < nb; i += NTHREADS) {
        int b = g_row_blocks[bstart + i];
        scols[i] = bcol_g[b] * 64;
        sblk[i]  = b * 64;
    }
    __syncthreads();

    if (wid == 8) {
        // ---------------- producer warp: all TMA issue ----------------
        if (lane == 0 && nb > 0) {
            int trow0 = tile * MT;
            for (int h = 0; h < nh; h++) {
                int s = h & 3;
                // init-phase-1 parity trick: first use of each stage passes
                // immediately; later uses need 8 consumer arrivals.
                uint32_t par = ((h >> 2) & 1) ^ 1u;
                MBARRIER_WAIT_PARITY(sb + MB_EMPTY + s * 8, par);
                uint32_t fullb = sb + MB_FULL + s * 8;
                uint32_t base  = sb + SMEM_STAGE0 + s * HSTAGE_BYTES;
                int blk = h >> 1, half = h & 1;
                MBARRIER_EXPECT_TX(fullb, HSTAGE_BYTES);
                TMA_LOAD_2D(base,         &tmx, scols[blk] + 32 * half, trow0,     fullb);
                TMA_LOAD_2D(base + HVOFF, &tmv, 32 * half,              sblk[blk], fullb);
            }
        }
    } else {
        // ---------------- compute warps ----------------
        float acc[2][4][4];
#pragma unroll
        for (int a = 0; a < 2; a++)
#pragma unroll
            for (int b = 0; b < 4; b++)
#pragma unroll
                for (int c = 0; c < 4; c++) acc[a][b][c] = 0.0f;

        if (nb > 0) {
            // per-lane fragment address bases (fixed across iterations)
            // A (x): ldmatrix.x4 quadrants (tf32 m16n8k8 A map)
            int arow0 = tg * 32 + (lane & 7) + ((lane >> 3) & 1) * 8;   // mt=0
            int kaddA = ((lane >> 4) & 1) * 4;
            uint32_t aoff0 = arow0 * 128, aoff1 = (arow0 + 16) * 128;
            uint32_t xra   = (uint32_t)((arow0 & 7) << 4);
            // B (v)
            int brow0 = (ng * 32) + ((lane >> 4) & 1) * 8 + (lane & 7);  // np=0
            int kaddB = ((lane >> 3) & 1) * 4;
            uint32_t boff0 = brow0 * 128, boff1 = (brow0 + 16) * 128;
            uint32_t xrb   = (uint32_t)((brow0 & 7) << 4);

            for (int h = 0; h < nh; h++) {
                int s = h & 3;
                MBARRIER_WAIT_PARITY(sb + MB_FULL + s * 8, (h >> 2) & 1);

                uint32_t pA = sb + SMEM_STAGE0 + s * HSTAGE_BYTES;
                uint32_t pB = pA + HVOFF;
#pragma unroll
                for (int kk = 0; kk < 4; kk++) {
                    uint32_t kp = kk * 8;
                    uint32_t a0[4], a1[4], b0[4], b1[4];
                    uint32_t kA = ((kp + kaddA) << 2) ^ xra;
                    uint32_t kB = ((kp + kaddB) << 2) ^ xrb;
                    LDSM4(a0[0], a0[1], a0[2], a0[3], pA + aoff0 + kA);
                    LDSM4(a1[0], a1[1], a1[2], a1[3], pA + aoff1 + kA);
                    LDSM4(b0[0], b0[1], b0[2], b0[3], pB + boff0 + kB);
                    LDSM4(b1[0], b1[1], b1[2], b1[3], pB + boff1 + kB);
                    round4(a0); round4(a1); round4(b0); round4(b1);
                    mma_tf32(acc[0][0], a0, b0[0], b0[1]);
                    mma_tf32(acc[0][1], a0, b0[2], b0[3]);
                    mma_tf32(acc[0][2], a0, b1[0], b1[1]);
                    mma_tf32(acc[0][3], a0, b1[2], b1[3]);
                    mma_tf32(acc[1][0], a1, b0[0], b0[1]);
                    mma_tf32(acc[1][1], a1, b0[2], b0[3]);
                    mma_tf32(acc[1][2], a1, b1[0], b1[1]);
                    mma_tf32(acc[1][3], a1, b1[2], b1[3]);
                }
                // all smem reads for this stage are complete (mma consumed the
                // ldmatrix results in program order); release the stage.
                if (lane == 0) MBARRIER_ARRIVE(sb + MB_EMPTY + s * 8);
            }
        }

        // ---------------- epilogue: bias + gelu + store ----------------
        const float* bs = (const float*)(smem + SMEM_BIAS);
        if (nb > 0) {
#pragma unroll
            for (int mt = 0; mt < 2; mt++) {
#pragma unroll
                for (int nt = 0; nt < 4; nt++) {
                    int row = tile * MT + tg * 32 + mt * 16 + (lane >> 2);
                    int colL = ng * 32 + nt * 8 + (lane & 3) * 2;
                    float bb0 = bs[colL], bb1 = bs[colL + 1];
                    float* p0 = y + (size_t)row * MDIM + rb * 64 + colL;
                    float* p1 = p0 + (size_t)8 * MDIM;
                    float2 o0, o1;
                    o0.x = gelu_tanh(acc[mt][nt][0] + bb0);
                    o0.y = gelu_tanh(acc[mt][nt][1] + bb1);
                    o1.x = gelu_tanh(acc[mt][nt][2] + bb0);
                    o1.y = gelu_tanh(acc[mt][nt][3] + bb1);
                    *reinterpret_cast<float2*>(p0) = o0;
                    *reinterpret_cast<float2*>(p1) = o1;
                }
            }
        } else {
            // no sparse blocks in this row: out = gelu(bias)
#pragma unroll
            for (int mt = 0; mt < 2; mt++) {
#pragma unroll
                for (int nt = 0; nt < 4; nt++) {
                    int row = tile * MT + tg * 32 + mt * 16 + (lane >> 2);
                    int colL = ng * 32 + nt * 8 + (lane & 3) * 2;
                    float* p0 = y + (size_t)row * MDIM + rb * 64 + colL;
                    float* p1 = p0 + (size_t)8 * MDIM;
                    float2 o0, o1;
                    o0.x = gelu_tanh(bs[colL]);
                    o0.y = gelu_tanh(bs[colL + 1]);
                    o1.x = o0.x;
                    o1.y = o0.y;
                    *reinterpret_cast<float2*>(p0) = o0;
                    *reinterpret_cast<float2*>(p1) = o1;
                }
            }
        }
    }

    __syncthreads();
    if (tid == 0) {
#pragma unroll
        for (int s = 0; s < 4; s++) {
            MBARRIER_INVAL(sb + MB_FULL + s * 8);
            MBARRIER_INVAL(sb + MB_EMPTY + s * 8);
        }
    }
}

// ---------------------------------------------------------------------------
// Launch (host). Tensor maps now point at the RAW inputs (rounding happens
// in-register inside fsl) — the rounding preprocess kernel is gone.
// ---------------------------------------------------------------------------
typedef CUresult (CUDAAPI *PFN_tmap_encode_t)(
    CUtensorMap*, CUtensorMapDataType, cuuint32_t, void*,
    const cuuint64_t*, const cuuint64_t*, const cuuint32_t*, const cuuint32_t*,
    CUtensorMapInterleave, CUtensorMapSwizzle, CUtensorMapL2promotion,
    CUtensorMapFloatOOBfill);

extern "C" void kernel_launch(void* const* d_in, const int* in_sizes, int n_in,
                              void* d_out, int out_size) {
    const float* x      = (const float*)d_in[0];
    const float* values = (const float*)d_in[1];
    const float* bias   = (const float*)d_in[2];
    const int*   brow   = (const int*)d_in[3];
    const int*   bcol   = (const int*)d_in[4];
    float*       y      = (float*)d_out;

    void* fn = nullptr;
    cudaDriverEntryPointQueryResult qr;
    cudaGetDriverEntryPoint("cuTensorMapEncodeTiled", &fn, cudaEnableDefault, &qr);
    PFN_tmap_encode_t enc = (PFN_tmap_encode_t)fn;

    alignas(64) CUtensorMap tmx;
    alignas(64) CUtensorMap tmv;
    {
        cuuint64_t dims[2]    = {KDIM, TOKENS};
        cuuint64_t strides[1] = {KDIM * sizeof(float)};
        cuuint32_t box[2]     = {32, MT};           // 128B inner (SW128)
        cuuint32_t es[2]      = {1, 1};
        enc(&tmx, CU_TENSOR_MAP_DATA_TYPE_FLOAT32, 2, (void*)x, dims, strides, box, es,
            CU_TENSOR_MAP_INTERLEAVE_NONE, CU_TENSOR_MAP_SWIZZLE_128B,
            CU_TENSOR_MAP_L2_PROMOTION_L2_256B, CU_TENSOR_MAP_FLOAT_OOB_FILL_NONE);
    }
    {
        cuuint64_t dims[2]    = {64, (cuuint64_t)NB * 64};
        cuuint64_t strides[1] = {64 * sizeof(float)};
        cuuint32_t box[2]     = {32, 64};
        cuuint32_t es[2]      = {1, 1};
        enc(&tmv, CU_TENSOR_MAP_DATA_TYPE_FLOAT32, 2, (void*)values, dims, strides, box, es,
            CU_TENSOR_MAP_INTERLEAVE_NONE, CU_TENSOR_MAP_SWIZZLE_128B,
            CU_TENSOR_MAP_L2_PROMOTION_L2_256B, CU_TENSOR_MAP_FLOAT_OOB_FILL_NONE);
    }

    cudaFuncSetAttribute(fsl_kernel, cudaFuncAttributeMaxDynamicSharedMemorySize, SMEM_TOTAL);

    build_lists_kernel<<<1, NB>>>(brow);

    dim3 grid(NTILE, NROW);
    fsl_kernel<<<grid, NTHREADS, SMEM_TOTAL>>>(tmx, tmv, bcol, bias, y);
}